// round 1
// baseline (speedup 1.0000x reference)
#include <cuda_runtime.h>

// RankOnePlanes: 1M points, 3x 1D bilinear table sample (L=128, C=32),
// polynomial feature combine, then 32->128 ReLU -> 128->1 MLP.
//
// Round 1: fp32 scalar kernel, one point per thread.
//  - tables + W1 + b1 + W2 staged in shared memory (tables padded to
//    36-float rows: 36%32=4 so random per-lane rows spread across banks)
//  - persistent grid (304 blocks) so smem staging cost is paid ~once
//  - layer 2 fused into the h-loop; feat[32] register resident

#define LTAB 128
#define CL 32
#define HDIM 128
#define TSTRIDE 36          // padded floats per table row (16B aligned, odd bank group)
#define NTHREADS 256
#define NBLOCKS 304         // ~2 per SM on 152-SM GB300

#define SMEM_FLOATS (3 * LTAB * TSTRIDE + HDIM * CL + HDIM + HDIM)
#define SMEM_BYTES (SMEM_FLOATS * 4)

__device__ __forceinline__ void sample_setup(float c, int& r0, int& r1,
                                             float& w0, float& w1) {
    float pos = (c + 1.0f) * 63.5f;   // (c+1)*0.5*(L-1), align_corners=True
    float f0  = floorf(pos);
    float fr  = pos - f0;
    int i0 = (int)f0;
    int i1 = i0 + 1;
    // zeros padding: OOB taps contribute 0 (mask matches reference exactly)
    w0 = ((unsigned)i0 < (unsigned)LTAB) ? (1.0f - fr) : 0.0f;
    w1 = ((unsigned)i1 < (unsigned)LTAB) ? fr : 0.0f;
    r0 = min(max(i0, 0), LTAB - 1);
    r1 = min(max(i1, 0), LTAB - 1);
}

__global__ __launch_bounds__(NTHREADS, 2)
void rank1_mlp_kernel(const float* __restrict__ coords,
                      const float* __restrict__ lines,
                      const float* __restrict__ W1,
                      const float* __restrict__ b1,
                      const float* __restrict__ W2,
                      const float* __restrict__ b2,
                      float* __restrict__ out, int M) {
    extern __shared__ float smem[];
    float* sT  = smem;                          // 3 * 128 * 36
    float* sW1 = sT + 3 * LTAB * TSTRIDE;       // 128 * 32 (unpadded; broadcast reads)
    float* sb1 = sW1 + HDIM * CL;               // 128
    float* sW2 = sb1 + HDIM;                    // 128

    // ---- stage constants into shared ----
    // tables: 3*128 rows of 32 floats = 3072 float4, scatter into padded rows
    for (int idx = threadIdx.x; idx < 3 * LTAB * 8; idx += NTHREADS) {
        int axis = idx / (LTAB * 8);
        int rem  = idx - axis * (LTAB * 8);
        int row  = rem >> 3;
        int j    = rem & 7;
        float4 v = reinterpret_cast<const float4*>(lines)[idx];
        *reinterpret_cast<float4*>(&sT[(axis * LTAB + row) * TSTRIDE + j * 4]) = v;
    }
    for (int idx = threadIdx.x; idx < HDIM * CL / 4; idx += NTHREADS)
        reinterpret_cast<float4*>(sW1)[idx] = reinterpret_cast<const float4*>(W1)[idx];
    for (int idx = threadIdx.x; idx < HDIM; idx += NTHREADS) {
        sb1[idx] = b1[idx];
        sW2[idx] = W2[idx];
    }
    __syncthreads();

    const float bias2 = __ldg(b2);
    const float invR  = 2.5f;      // 1/0.4
    const float invR2 = 6.25f;     // 1/0.16

    for (int m = blockIdx.x * NTHREADS + threadIdx.x; m < M;
         m += gridDim.x * NTHREADS) {
        float cx = coords[3 * m + 0];
        float cy = coords[3 * m + 1];
        float cz = coords[3 * m + 2];

        int xr0, xr1, yr0, yr1, zr0, zr1;
        float xw0, xw1, yw0, yw1, zw0, zw1;
        sample_setup(cx, xr0, xr1, xw0, xw1);
        sample_setup(cy, yr0, yr1, yw0, yw1);
        sample_setup(cz, zr0, zr1, zw0, zw1);

        const float* tx0 = &sT[(0 * LTAB + xr0) * TSTRIDE];
        const float* tx1 = &sT[(0 * LTAB + xr1) * TSTRIDE];
        const float* ty0 = &sT[(1 * LTAB + yr0) * TSTRIDE];
        const float* ty1 = &sT[(1 * LTAB + yr1) * TSTRIDE];
        const float* tz0 = &sT[(2 * LTAB + zr0) * TSTRIDE];
        const float* tz1 = &sT[(2 * LTAB + zr1) * TSTRIDE];

        float feat[CL];

#define FEAT_COMP(k, X0, X1, Y0, Y1, Z0, Z1)                        \
        {                                                           \
            float xv = fmaf((X1), xw1, (X0) * xw0);                 \
            float yv = fmaf((Y1), yw1, (Y0) * yw0);                 \
            float zv = fmaf((Z1), zw1, (Z0) * zw0);                 \
            float s  = xv + yv + zv;                                \
            float xy = xv * yv;                                     \
            float p2 = fmaf(xv, zv, xy);                            \
            p2 = fmaf(yv, zv, p2);                                  \
            float p3 = xy * zv;                                     \
            float f  = fmaf(p2, invR, s);                           \
            feat[cg * 4 + (k)] = fmaf(p3, invR2, f);                \
        }

#pragma unroll
        for (int cg = 0; cg < 8; cg++) {
            float4 a0 = *reinterpret_cast<const float4*>(&tx0[cg * 4]);
            float4 a1 = *reinterpret_cast<const float4*>(&tx1[cg * 4]);
            float4 c0 = *reinterpret_cast<const float4*>(&ty0[cg * 4]);
            float4 c1 = *reinterpret_cast<const float4*>(&ty1[cg * 4]);
            float4 e0 = *reinterpret_cast<const float4*>(&tz0[cg * 4]);
            float4 e1 = *reinterpret_cast<const float4*>(&tz1[cg * 4]);
            FEAT_COMP(0, a0.x, a1.x, c0.x, c1.x, e0.x, e1.x);
            FEAT_COMP(1, a0.y, a1.y, c0.y, c1.y, e0.y, e1.y);
            FEAT_COMP(2, a0.z, a1.z, c0.z, c1.z, e0.z, e1.z);
            FEAT_COMP(3, a0.w, a1.w, c0.w, c1.w, e0.w, e1.w);
        }
#undef FEAT_COMP

        // ---- 32 -> 128 ReLU -> 1, layer-2 fused ----
        float o = bias2;
#pragma unroll 4
        for (int h = 0; h < HDIM; h++) {
            const float4* wr = reinterpret_cast<const float4*>(&sW1[h * CL]);
            float a = sb1[h];
            float b = 0.0f;
#pragma unroll
            for (int cg = 0; cg < 8; cg += 2) {
                float4 wA = wr[cg];
                a = fmaf(wA.x, feat[4 * cg + 0], a);
                a = fmaf(wA.y, feat[4 * cg + 1], a);
                a = fmaf(wA.z, feat[4 * cg + 2], a);
                a = fmaf(wA.w, feat[4 * cg + 3], a);
                float4 wB = wr[cg + 1];
                b = fmaf(wB.x, feat[4 * cg + 4], b);
                b = fmaf(wB.y, feat[4 * cg + 5], b);
                b = fmaf(wB.z, feat[4 * cg + 6], b);
                b = fmaf(wB.w, feat[4 * cg + 7], b);
            }
            float hv = fmaxf(a + b, 0.0f);
            o = fmaf(hv, sW2[h], o);
        }
        out[m] = o;
    }
}

extern "C" void kernel_launch(void* const* d_in, const int* in_sizes, int n_in,
                              void* d_out, int out_size) {
    const float* coords = (const float*)d_in[0];
    const float* lines  = (const float*)d_in[1];
    const float* W1     = (const float*)d_in[2];
    const float* b1     = (const float*)d_in[3];
    const float* W2     = (const float*)d_in[4];
    const float* b2     = (const float*)d_in[5];
    float* out = (float*)d_out;

    int M = in_sizes[0] / 3;

    cudaFuncSetAttribute(rank1_mlp_kernel,
                         cudaFuncAttributeMaxDynamicSharedMemorySize, SMEM_BYTES);

    rank1_mlp_kernel<<<NBLOCKS, NTHREADS, SMEM_BYTES>>>(
        coords, lines, W1, b1, W2, b2, out, M);
}

// round 2
// speedup vs baseline: 1.3840x; 1.3840x over previous
#include <cuda_runtime.h>

// RankOnePlanes: 1M points, 3x 1D bilinear table sample (L=128, C=32),
// polynomial combine, 32->128 ReLU -> 128->1 MLP.
//
// Round 2: flip the R1 bottleneck (L1/shared wavefronts at 84.7%):
//  - P=2 points per thread: each W1 LDS.128 serves 2 points (halves LDS/pt)
//  - fma.rn.f32x2 over channel PAIRS: weight pairs come directly out of
//    LDS.128 as adjacent register pairs (zero packing cost); feature pairs
//    packed once per point. Bit-identical fp32 math, half the fma-pipe ops.

#define LTAB 128
#define CL 32
#define HDIM 128
#define TSTRIDE 36
#define NTHREADS 192
#define NBLOCKS 304

#define SMEM_FLOATS (3 * LTAB * TSTRIDE + HDIM * CL + HDIM + HDIM)
#define SMEM_BYTES (SMEM_FLOATS * 4)

typedef unsigned long long ull;

__device__ __forceinline__ ull pk2(float lo, float hi) {
    ull r;
    asm("mov.b64 %0, {%1, %2};" : "=l"(r) : "f"(lo), "f"(hi));
    return r;
}
__device__ __forceinline__ void unpk2(float& lo, float& hi, ull v) {
    asm("mov.b64 {%0, %1}, %2;" : "=f"(lo), "=f"(hi) : "l"(v));
}
__device__ __forceinline__ ull fma2(ull a, ull b, ull c) {
    ull d;
    asm("fma.rn.f32x2 %0, %1, %2, %3;" : "=l"(d) : "l"(a), "l"(b), "l"(c));
    return d;
}
__device__ __forceinline__ ull add2(ull a, ull b) {
    ull d;
    asm("add.rn.f32x2 %0, %1, %2;" : "=l"(d) : "l"(a), "l"(b));
    return d;
}

__device__ __forceinline__ void sample_setup(float c, int& r0, int& r1,
                                             float& w0, float& w1) {
    float pos = (c + 1.0f) * 63.5f;
    float f0  = floorf(pos);
    float fr  = pos - f0;
    int i0 = (int)f0;
    int i1 = i0 + 1;
    w0 = ((unsigned)i0 < (unsigned)LTAB) ? (1.0f - fr) : 0.0f;
    w1 = ((unsigned)i1 < (unsigned)LTAB) ? fr : 0.0f;
    r0 = min(max(i0, 0), LTAB - 1);
    r1 = min(max(i1, 0), LTAB - 1);
}

// Compute the 32 polynomial features of one point, packed as 16 f32x2 pairs.
__device__ __forceinline__ void compute_feats(const float* __restrict__ sT,
                                              float cx, float cy, float cz,
                                              ull* __restrict__ F) {
    int xr0, xr1, yr0, yr1, zr0, zr1;
    float xw0, xw1, yw0, yw1, zw0, zw1;
    sample_setup(cx, xr0, xr1, xw0, xw1);
    sample_setup(cy, yr0, yr1, yw0, yw1);
    sample_setup(cz, zr0, zr1, zw0, zw1);

    const float* tx0 = &sT[(0 * LTAB + xr0) * TSTRIDE];
    const float* tx1 = &sT[(0 * LTAB + xr1) * TSTRIDE];
    const float* ty0 = &sT[(1 * LTAB + yr0) * TSTRIDE];
    const float* ty1 = &sT[(1 * LTAB + yr1) * TSTRIDE];
    const float* tz0 = &sT[(2 * LTAB + zr0) * TSTRIDE];
    const float* tz1 = &sT[(2 * LTAB + zr1) * TSTRIDE];

    const float invR  = 2.5f;   // 1/0.4
    const float invR2 = 6.25f;  // 1/0.16

#define FEAT1(OUT, X0, X1, Y0, Y1, Z0, Z1)                  \
    {                                                       \
        float xv = fmaf((X1), xw1, (X0) * xw0);             \
        float yv = fmaf((Y1), yw1, (Y0) * yw0);             \
        float zv = fmaf((Z1), zw1, (Z0) * zw0);             \
        float s  = xv + yv + zv;                            \
        float xy = xv * yv;                                 \
        float p2 = fmaf(xv, zv, xy);                        \
        p2 = fmaf(yv, zv, p2);                              \
        float p3 = xy * zv;                                 \
        float f  = fmaf(p2, invR, s);                       \
        OUT = fmaf(p3, invR2, f);                           \
    }

#pragma unroll
    for (int cg = 0; cg < 8; cg++) {
        float4 a0 = *reinterpret_cast<const float4*>(&tx0[cg * 4]);
        float4 a1 = *reinterpret_cast<const float4*>(&tx1[cg * 4]);
        float4 c0 = *reinterpret_cast<const float4*>(&ty0[cg * 4]);
        float4 c1 = *reinterpret_cast<const float4*>(&ty1[cg * 4]);
        float4 e0 = *reinterpret_cast<const float4*>(&tz0[cg * 4]);
        float4 e1 = *reinterpret_cast<const float4*>(&tz1[cg * 4]);
        float f0, f1, f2, f3;
        FEAT1(f0, a0.x, a1.x, c0.x, c1.x, e0.x, e1.x);
        FEAT1(f1, a0.y, a1.y, c0.y, c1.y, e0.y, e1.y);
        FEAT1(f2, a0.z, a1.z, c0.z, c1.z, e0.z, e1.z);
        FEAT1(f3, a0.w, a1.w, c0.w, c1.w, e0.w, e1.w);
        F[2 * cg + 0] = pk2(f0, f1);
        F[2 * cg + 1] = pk2(f2, f3);
    }
#undef FEAT1
}

__global__ __launch_bounds__(NTHREADS, 2)
void rank1_mlp_kernel(const float* __restrict__ coords,
                      const float* __restrict__ lines,
                      const float* __restrict__ W1,
                      const float* __restrict__ b1,
                      const float* __restrict__ W2,
                      const float* __restrict__ b2,
                      float* __restrict__ out, int M) {
    extern __shared__ float smem[];
    float* sT  = smem;                      // 3 * 128 * 36
    float* sW1 = sT + 3 * LTAB * TSTRIDE;   // 128 * 32
    float* sb1 = sW1 + HDIM * CL;           // 128
    float* sW2 = sb1 + HDIM;                // 128

    // ---- stage constants ----
    for (int idx = threadIdx.x; idx < 3 * LTAB * 8; idx += NTHREADS) {
        int axis = idx / (LTAB * 8);
        int rem  = idx - axis * (LTAB * 8);
        int row  = rem >> 3;
        int j    = rem & 7;
        float4 v = reinterpret_cast<const float4*>(lines)[idx];
        *reinterpret_cast<float4*>(&sT[(axis * LTAB + row) * TSTRIDE + j * 4]) = v;
    }
    for (int idx = threadIdx.x; idx < HDIM * CL / 4; idx += NTHREADS)
        reinterpret_cast<float4*>(sW1)[idx] = reinterpret_cast<const float4*>(W1)[idx];
    for (int idx = threadIdx.x; idx < HDIM; idx += NTHREADS) {
        sb1[idx] = b1[idx];
        sW2[idx] = W2[idx];
    }
    __syncthreads();

    const float bias2 = __ldg(b2);
    const ulonglong2* __restrict__ sw = reinterpret_cast<const ulonglong2*>(sW1);
    const float4* __restrict__ sb1v = reinterpret_cast<const float4*>(sb1);
    const float4* __restrict__ sW2v = reinterpret_cast<const float4*>(sW2);

    const int stride = NBLOCKS * NTHREADS * 2;
    for (int m0 = (blockIdx.x * NTHREADS + threadIdx.x) * 2; m0 < M;
         m0 += stride) {
        int m1 = (m0 + 1 < M) ? m0 + 1 : m0;

        float cx0 = coords[3 * m0 + 0];
        float cy0 = coords[3 * m0 + 1];
        float cz0 = coords[3 * m0 + 2];
        float cx1 = coords[3 * m1 + 0];
        float cy1 = coords[3 * m1 + 1];
        float cz1 = coords[3 * m1 + 2];

        ull F0[16], F1[16];
        compute_feats(sT, cx0, cy0, cz0, F0);
        compute_feats(sT, cx1, cy1, cz1, F1);

        float o0 = bias2, o1 = bias2;

        for (int h4 = 0; h4 < HDIM / 4; h4++) {
            float4 bb4 = sb1v[h4];
            float4 ww4 = sW2v[h4];
#pragma unroll
            for (int j = 0; j < 4; j++) {
                int h = h4 * 4 + j;
                const ulonglong2* wp = sw + h * 8;
                ull aA = 0, aB = 0, bA = 0, bB = 0;
#pragma unroll
                for (int q = 0; q < 8; q++) {
                    ulonglong2 w = wp[q];   // LDS.128 -> 2 weight pairs, free
                    aA = fma2(w.x, F0[2 * q + 0], aA);
                    aB = fma2(w.y, F0[2 * q + 1], aB);
                    bA = fma2(w.x, F1[2 * q + 0], bA);
                    bB = fma2(w.y, F1[2 * q + 1], bB);
                }
                ull s0 = add2(aA, aB);
                ull s1 = add2(bA, bB);
                float l0, u0, l1, u1;
                unpk2(l0, u0, s0);
                unpk2(l1, u1, s1);
                float bb = (j == 0) ? bb4.x : (j == 1) ? bb4.y
                                           : (j == 2) ? bb4.z : bb4.w;
                float ww = (j == 0) ? ww4.x : (j == 1) ? ww4.y
                                           : (j == 2) ? ww4.z : ww4.w;
                float hv0 = fmaxf((l0 + u0) + bb, 0.0f);
                float hv1 = fmaxf((l1 + u1) + bb, 0.0f);
                o0 = fmaf(hv0, ww, o0);
                o1 = fmaf(hv1, ww, o1);
            }
        }

        out[m0] = o0;
        if (m0 + 1 < M) out[m0 + 1] = o1;
    }
}

extern "C" void kernel_launch(void* const* d_in, const int* in_sizes, int n_in,
                              void* d_out, int out_size) {
    const float* coords = (const float*)d_in[0];
    const float* lines  = (const float*)d_in[1];
    const float* W1     = (const float*)d_in[2];
    const float* b1     = (const float*)d_in[3];
    const float* W2     = (const float*)d_in[4];
    const float* b2     = (const float*)d_in[5];
    float* out = (float*)d_out;

    int M = in_sizes[0] / 3;

    cudaFuncSetAttribute(rank1_mlp_kernel,
                         cudaFuncAttributeMaxDynamicSharedMemorySize, SMEM_BYTES);

    rank1_mlp_kernel<<<NBLOCKS, NTHREADS, SMEM_BYTES>>>(
        coords, lines, W1, b1, W2, b2, out, M);
}

// round 4
// speedup vs baseline: 3.1511x; 2.2767x over previous
#include <cuda_runtime.h>
#include <cuda_bf16.h>
#include <cstdint>

// RankOnePlanes via warp-level tensor cores (mma.sync bf16, sm_80+ PTX --
// tcgen05 is rejected by this toolchain's sm_103 PTX target).
//
// feat = fh + fl (split bf16), W1 = wh + wl.  H ~= fh*wh + fh*wl + fl*wh
// (6 HMMA k16 chunks per 16x8 tile, fp32 accum; error ~2^-16).
// Warp-scoped tiles of 32 points: feats -> STS A -> ldmatrix -> 192 HMMA
// -> fused relu+W2 epilogue on C fragments -> shfl-reduce -> STG.

#define LTAB 128
#define CL 32
#define HDIM 128
#define TSTRIDE 36
#define NTHREADS 256
#define WARPS_PER_CTA 8
#define NBLOCKS 304
#define ROWPAD 144   // bytes per 64-bf16 row (+16B pad: conflict-free ldmatrix)

// ---- smem byte offsets ----
#define SM_TAB 0                         // 3*128*36*4 = 55296
#define SM_W1  55296                     // 128 rows x 144 B = 18432
#define SM_B1  (55296 + 18432)           // 512
#define SM_W2  (SM_B1 + 512)             // 512
#define SM_A   (SM_W2 + 512)             // 8 warps x 32 x 144 = 36864
#define SMEM_BYTES (SM_A + WARPS_PER_CTA * 32 * ROWPAD)

__device__ __forceinline__ uint32_t smem_u32(const void* p) {
    uint32_t a;
    asm("{ .reg .u64 t; cvta.to.shared.u64 t, %1; cvt.u32.u64 %0, t; }"
        : "=r"(a) : "l"(p));
    return a;
}
__device__ __forceinline__ void ldsm_x4(uint32_t addr, uint32_t* r) {
    asm volatile("ldmatrix.sync.aligned.m8n8.x4.shared.b16 {%0,%1,%2,%3}, [%4];"
                 : "=r"(r[0]), "=r"(r[1]), "=r"(r[2]), "=r"(r[3]) : "r"(addr));
}
__device__ __forceinline__ void mma_bf16(float4& c, const uint32_t* a,
                                         const uint32_t* b) {
    asm volatile(
        "mma.sync.aligned.m16n8k16.row.col.f32.bf16.bf16.f32 "
        "{%0,%1,%2,%3}, {%4,%5,%6,%7}, {%8,%9}, {%0,%1,%2,%3};"
        : "+f"(c.x), "+f"(c.y), "+f"(c.z), "+f"(c.w)
        : "r"(a[0]), "r"(a[1]), "r"(a[2]), "r"(a[3]), "r"(b[0]), "r"(b[1]));
}
__device__ __forceinline__ uint32_t pkbf(float a, float b) {
    __nv_bfloat162 t = __floats2bfloat162_rn(a, b);
    return *reinterpret_cast<uint32_t*>(&t);
}

__device__ __forceinline__ void sample_setup(float c, int& r0, int& r1,
                                             float& w0, float& w1) {
    float pos = (c + 1.0f) * 63.5f;
    float f0  = floorf(pos);
    float fr  = pos - f0;
    int i0 = (int)f0;
    int i1 = i0 + 1;
    w0 = ((unsigned)i0 < (unsigned)LTAB) ? (1.0f - fr) : 0.0f;
    w1 = ((unsigned)i1 < (unsigned)LTAB) ? fr : 0.0f;
    r0 = min(max(i0, 0), LTAB - 1);
    r1 = min(max(i1, 0), LTAB - 1);
}

__device__ __forceinline__ void compute_feats(const float* __restrict__ sT,
                                              float cx, float cy, float cz,
                                              float* __restrict__ feat) {
    int xr0, xr1, yr0, yr1, zr0, zr1;
    float xw0, xw1, yw0, yw1, zw0, zw1;
    sample_setup(cx, xr0, xr1, xw0, xw1);
    sample_setup(cy, yr0, yr1, yw0, yw1);
    sample_setup(cz, zr0, zr1, zw0, zw1);

    const float* tx0 = &sT[(0 * LTAB + xr0) * TSTRIDE];
    const float* tx1 = &sT[(0 * LTAB + xr1) * TSTRIDE];
    const float* ty0 = &sT[(1 * LTAB + yr0) * TSTRIDE];
    const float* ty1 = &sT[(1 * LTAB + yr1) * TSTRIDE];
    const float* tz0 = &sT[(2 * LTAB + zr0) * TSTRIDE];
    const float* tz1 = &sT[(2 * LTAB + zr1) * TSTRIDE];

    const float invR  = 2.5f;
    const float invR2 = 6.25f;

#define FEAT1(OUT, X0, X1, Y0, Y1, Z0, Z1)                  \
    {                                                       \
        float xv = fmaf((X1), xw1, (X0) * xw0);             \
        float yv = fmaf((Y1), yw1, (Y0) * yw0);             \
        float zv = fmaf((Z1), zw1, (Z0) * zw0);             \
        float s  = xv + yv + zv;                            \
        float xy = xv * yv;                                 \
        float p2 = fmaf(xv, zv, xy);                        \
        p2 = fmaf(yv, zv, p2);                              \
        float p3 = xy * zv;                                 \
        float f  = fmaf(p2, invR, s);                       \
        OUT = fmaf(p3, invR2, f);                           \
    }
#pragma unroll
    for (int cg = 0; cg < 8; cg++) {
        float4 a0 = *reinterpret_cast<const float4*>(&tx0[cg * 4]);
        float4 a1 = *reinterpret_cast<const float4*>(&tx1[cg * 4]);
        float4 c0 = *reinterpret_cast<const float4*>(&ty0[cg * 4]);
        float4 c1 = *reinterpret_cast<const float4*>(&ty1[cg * 4]);
        float4 e0 = *reinterpret_cast<const float4*>(&tz0[cg * 4]);
        float4 e1 = *reinterpret_cast<const float4*>(&tz1[cg * 4]);
        FEAT1(feat[4 * cg + 0], a0.x, a1.x, c0.x, c1.x, e0.x, e1.x);
        FEAT1(feat[4 * cg + 1], a0.y, a1.y, c0.y, c1.y, e0.y, e1.y);
        FEAT1(feat[4 * cg + 2], a0.z, a1.z, c0.z, c1.z, e0.z, e1.z);
        FEAT1(feat[4 * cg + 3], a0.w, a1.w, c0.w, c1.w, e0.w, e1.w);
    }
#undef FEAT1
}

__global__ __launch_bounds__(NTHREADS, 2)
void rank1_hmma_kernel(const float* __restrict__ coords,
                       const float* __restrict__ lines,
                       const float* __restrict__ W1,
                       const float* __restrict__ b1,
                       const float* __restrict__ W2,
                       const float* __restrict__ b2,
                       float* __restrict__ out, int M) {
    extern __shared__ char smc[];
    const uint32_t sb = smem_u32(smc);
    float* sT  = reinterpret_cast<float*>(smc + SM_TAB);
    float* sb1 = reinterpret_cast<float*>(smc + SM_B1);
    float* sW2 = reinterpret_cast<float*>(smc + SM_W2);

    const int tid  = threadIdx.x;
    const int wid  = tid >> 5;
    const int lane = tid & 31;

    // ---- stage tables (padded rows) ----
    for (int idx = tid; idx < 3 * LTAB * 8; idx += NTHREADS) {
        int axis = idx / (LTAB * 8);
        int rem  = idx - axis * (LTAB * 8);
        int row  = rem >> 3;
        int j    = rem & 7;
        float4 v = reinterpret_cast<const float4*>(lines)[idx];
        *reinterpret_cast<float4*>(&sT[(axis * LTAB + row) * TSTRIDE + j * 4]) = v;
    }
    // ---- stage b1, W2 and split-bf16 W1 = [wh | wl], rows padded 144 B ----
    if (tid < HDIM) {
        sb1[tid] = b1[tid];
        sW2[tid] = W2[tid];
        char* dst = smc + SM_W1 + tid * ROWPAD;
        const float4* wrow = reinterpret_cast<const float4*>(W1 + tid * CL);
#pragma unroll
        for (int j = 0; j < 8; j += 2) {
            float4 wa = wrow[j], wb = wrow[j + 1];
            float ha0 = __bfloat162float(__float2bfloat16(wa.x));
            float ha1 = __bfloat162float(__float2bfloat16(wa.y));
            float ha2 = __bfloat162float(__float2bfloat16(wa.z));
            float ha3 = __bfloat162float(__float2bfloat16(wa.w));
            float hb0 = __bfloat162float(__float2bfloat16(wb.x));
            float hb1 = __bfloat162float(__float2bfloat16(wb.y));
            float hb2 = __bfloat162float(__float2bfloat16(wb.z));
            float hb3 = __bfloat162float(__float2bfloat16(wb.w));
            uint4 vh = make_uint4(pkbf(ha0, ha1), pkbf(ha2, ha3),
                                  pkbf(hb0, hb1), pkbf(hb2, hb3));
            uint4 vl = make_uint4(pkbf(wa.x - ha0, wa.y - ha1),
                                  pkbf(wa.z - ha2, wa.w - ha3),
                                  pkbf(wb.x - hb0, wb.y - hb1),
                                  pkbf(wb.z - hb2, wb.w - hb3));
            *reinterpret_cast<uint4*>(dst + j * 8)      = vh;
            *reinterpret_cast<uint4*>(dst + 64 + j * 8) = vl;
        }
    }
    __syncthreads();

    const float bias2 = __ldg(b2);
    const uint32_t sbA  = sb + SM_A + wid * (32 * ROWPAD);
    const uint32_t sbW1 = sb + SM_W1;

    // per-lane ldmatrix row addresses (constant across tiles)
    const uint32_t a_addr_base =
        sbA + (uint32_t)(lane & 15) * ROWPAD + (uint32_t)(lane >> 4) * 16;
    const uint32_t b_row = (uint32_t)((lane & 7) + ((lane & 16) ? 8 : 0));
    const uint32_t b_addr_base =
        sbW1 + b_row * ROWPAD + (uint32_t)((lane & 8) ? 16 : 0);

    const int warp_gid     = blockIdx.x * WARPS_PER_CTA + wid;
    const int total_warps  = NBLOCKS * WARPS_PER_CTA;
    const int tiles        = (M + 31) >> 5;

    for (int t = warp_gid; t < tiles; t += total_warps) {
        const int p  = t * 32 + lane;
        const int pc = (p < M) ? p : (M - 1);

        // ---- features for this lane's point ----
        float cx = coords[3 * pc + 0];
        float cy = coords[3 * pc + 1];
        float cz = coords[3 * pc + 2];
        float feat[CL];
        compute_feats(sT, cx, cy, cz, feat);

        // ---- STS split-bf16 A row (lane = row): [fh 32 | fl 32] ----
        {
            char* dst = smc + SM_A + wid * (32 * ROWPAD) + lane * ROWPAD;
#pragma unroll
            for (int j = 0; j < 8; j += 2) {
                float f0 = feat[4 * j + 0], f1 = feat[4 * j + 1];
                float f2 = feat[4 * j + 2], f3 = feat[4 * j + 3];
                float f4 = feat[4 * j + 4], f5 = feat[4 * j + 5];
                float f6 = feat[4 * j + 6], f7 = feat[4 * j + 7];
                float h0 = __bfloat162float(__float2bfloat16(f0));
                float h1 = __bfloat162float(__float2bfloat16(f1));
                float h2 = __bfloat162float(__float2bfloat16(f2));
                float h3 = __bfloat162float(__float2bfloat16(f3));
                float h4 = __bfloat162float(__float2bfloat16(f4));
                float h5 = __bfloat162float(__float2bfloat16(f5));
                float h6 = __bfloat162float(__float2bfloat16(f6));
                float h7 = __bfloat162float(__float2bfloat16(f7));
                uint4 vh = make_uint4(pkbf(h0, h1), pkbf(h2, h3),
                                      pkbf(h4, h5), pkbf(h6, h7));
                uint4 vl = make_uint4(pkbf(f0 - h0, f1 - h1),
                                      pkbf(f2 - h2, f3 - h3),
                                      pkbf(f4 - h4, f5 - h5),
                                      pkbf(f6 - h6, f7 - h7));
                *reinterpret_cast<uint4*>(dst + j * 8)      = vh;
                *reinterpret_cast<uint4*>(dst + 64 + j * 8) = vl;
            }
        }
        __syncwarp();

        // ---- load A fragments: 2 row-tiles x 4 k16-chunks ----
        uint32_t a[2][4][4];
#pragma unroll
        for (int rt = 0; rt < 2; rt++)
#pragma unroll
            for (int kc = 0; kc < 4; kc++)
                ldsm_x4(a_addr_base + (uint32_t)(rt * 16) * ROWPAD +
                            (uint32_t)(kc * 32),
                        a[rt][kc]);

        float oacc0 = 0.0f, oacc1 = 0.0f, oacc2 = 0.0f, oacc3 = 0.0f;
        const int colb = (lane & 3) * 2;

        // ---- n-pairs: 16 cols each ----
#pragma unroll
        for (int np = 0; np < 8; np++) {
            uint32_t b[4][4];  // [k16 chunk][ntile0 b0,b1, ntile1 b0,b1]
#pragma unroll
            for (int kc = 0; kc < 4; kc++)
                ldsm_x4(b_addr_base + (uint32_t)(np * 16) * ROWPAD +
                            (uint32_t)(kc * 32),
                        b[kc]);

            float4 c[2][2];
#pragma unroll
            for (int rt = 0; rt < 2; rt++)
#pragma unroll
                for (int nt = 0; nt < 2; nt++)
                    c[rt][nt] = make_float4(0.f, 0.f, 0.f, 0.f);

            // fh*wh: (A0,B0),(A1,B1); fh*wl: (A0,B2),(A1,B3); fl*wh: (A2,B0),(A3,B1)
#pragma unroll
            for (int rt = 0; rt < 2; rt++) {
#pragma unroll
                for (int nt = 0; nt < 2; nt++) {
                    mma_bf16(c[rt][nt], a[rt][0], &b[0][nt * 2]);
                    mma_bf16(c[rt][nt], a[rt][1], &b[1][nt * 2]);
                    mma_bf16(c[rt][nt], a[rt][0], &b[2][nt * 2]);
                    mma_bf16(c[rt][nt], a[rt][1], &b[3][nt * 2]);
                    mma_bf16(c[rt][nt], a[rt][2], &b[0][nt * 2]);
                    mma_bf16(c[rt][nt], a[rt][3], &b[1][nt * 2]);
                }
            }

            // ---- fused epilogue on fragments ----
            int col0 = np * 16 + colb;
            float2 b1a = *reinterpret_cast<const float2*>(&sb1[col0]);
            float2 w2a = *reinterpret_cast<const float2*>(&sW2[col0]);
            float2 b1b = *reinterpret_cast<const float2*>(&sb1[col0 + 8]);
            float2 w2b = *reinterpret_cast<const float2*>(&sW2[col0 + 8]);
#pragma unroll
            for (int rt = 0; rt < 2; rt++) {
                float lo = 0.0f, hi = 0.0f;
                lo = fmaf(fmaxf(c[rt][0].x + b1a.x, 0.f), w2a.x, lo);
                lo = fmaf(fmaxf(c[rt][0].y + b1a.y, 0.f), w2a.y, lo);
                lo = fmaf(fmaxf(c[rt][1].x + b1b.x, 0.f), w2b.x, lo);
                lo = fmaf(fmaxf(c[rt][1].y + b1b.y, 0.f), w2b.y, lo);
                hi = fmaf(fmaxf(c[rt][0].z + b1a.x, 0.f), w2a.x, hi);
                hi = fmaf(fmaxf(c[rt][0].w + b1a.y, 0.f), w2a.y, hi);
                hi = fmaf(fmaxf(c[rt][1].z + b1b.x, 0.f), w2b.x, hi);
                hi = fmaf(fmaxf(c[rt][1].w + b1b.y, 0.f), w2b.y, hi);
                if (rt == 0) { oacc0 += lo; oacc1 += hi; }
                else         { oacc2 += lo; oacc3 += hi; }
            }
        }

        // ---- reduce over the 4 lanes sharing each row ----
        oacc0 += __shfl_xor_sync(0xffffffffu, oacc0, 1);
        oacc0 += __shfl_xor_sync(0xffffffffu, oacc0, 2);
        oacc1 += __shfl_xor_sync(0xffffffffu, oacc1, 1);
        oacc1 += __shfl_xor_sync(0xffffffffu, oacc1, 2);
        oacc2 += __shfl_xor_sync(0xffffffffu, oacc2, 1);
        oacc2 += __shfl_xor_sync(0xffffffffu, oacc2, 2);
        oacc3 += __shfl_xor_sync(0xffffffffu, oacc3, 1);
        oacc3 += __shfl_xor_sync(0xffffffffu, oacc3, 2);

        if ((lane & 3) == 0) {
            int r  = lane >> 2;
            int pb = t * 32;
            if (pb + r      < M) out[pb + r]      = oacc0 + bias2;
            if (pb + r + 8  < M) out[pb + r + 8]  = oacc1 + bias2;
            if (pb + r + 16 < M) out[pb + r + 16] = oacc2 + bias2;
            if (pb + r + 24 < M) out[pb + r + 24] = oacc3 + bias2;
        }
        __syncwarp();
    }
}

extern "C" void kernel_launch(void* const* d_in, const int* in_sizes, int n_in,
                              void* d_out, int out_size) {
    const float* coords = (const float*)d_in[0];
    const float* lines  = (const float*)d_in[1];
    const float* W1     = (const float*)d_in[2];
    const float* b1     = (const float*)d_in[3];
    const float* W2     = (const float*)d_in[4];
    const float* b2     = (const float*)d_in[5];
    float* out = (float*)d_out;

    int M = in_sizes[0] / 3;

    cudaFuncSetAttribute(rank1_hmma_kernel,
                         cudaFuncAttributeMaxDynamicSharedMemorySize, SMEM_BYTES);

    rank1_hmma_kernel<<<NBLOCKS, NTHREADS, SMEM_BYTES>>>(
        coords, lines, W1, b1, W2, b2, out, M);
}

// round 5
// speedup vs baseline: 3.2817x; 1.0415x over previous
#include <cuda_runtime.h>
#include <cuda_bf16.h>
#include <cstdint>

// RankOnePlanes, HMMA bf16-split path, round 5.
// R4 bottleneck was L1 (78%), dominated by table-gather bank conflicts and
// the A smem round-trip. Changes:
//  - table stored per-lane-quarter: each row = 4 blocks of 8 channels
//    {2q,2q+1,2q+8,2q+9,2q+16,2q+17,2q+24,2q+25}, so each lane fetches its
//    MMA-fragment channels with 2 LDS.128 per tap; per-instruction bank
//    phases drop ~8.3 -> ~5.1.
//  - A fragments built directly in registers from per-lane feats
//    (4 points x 8 channels per lane): no STS A, no ldmatrix A, no A buffer.
//  - 6-MMA split-bf16 GEMM + fused relu/W2 epilogue unchanged.

#define LTAB 128
#define CL 32
#define HDIM 128
#define TSTRIDE 36   // floats per table row (4 x 32B quarter-blocks + 16B pad)
#define NTHREADS 256
#define WARPS_PER_CTA 8
#define NBLOCKS 304
#define ROWPAD 144   // W1 row bytes (64 bf16 + 16B pad)

// ---- smem byte offsets ----
#define SM_TAB 0                          // 3*128*36*4 = 55296
#define SM_W1  55296                      // 128 * 144  = 18432
#define SM_B1  (55296 + 18432)            // 512
#define SM_W2  (SM_B1 + 512)              // 512
#define SMEM_BYTES (SM_W2 + 512)          // 74752

__device__ __forceinline__ uint32_t smem_u32(const void* p) {
    uint32_t a;
    asm("{ .reg .u64 t; cvta.to.shared.u64 t, %1; cvt.u32.u64 %0, t; }"
        : "=r"(a) : "l"(p));
    return a;
}
__device__ __forceinline__ void ldsm_x4(uint32_t addr, uint32_t* r) {
    asm volatile("ldmatrix.sync.aligned.m8n8.x4.shared.b16 {%0,%1,%2,%3}, [%4];"
                 : "=r"(r[0]), "=r"(r[1]), "=r"(r[2]), "=r"(r[3]) : "r"(addr));
}
__device__ __forceinline__ void mma_bf16(float4& c, const uint32_t* a,
                                         const uint32_t* b) {
    asm volatile(
        "mma.sync.aligned.m16n8k16.row.col.f32.bf16.bf16.f32 "
        "{%0,%1,%2,%3}, {%4,%5,%6,%7}, {%8,%9}, {%0,%1,%2,%3};"
        : "+f"(c.x), "+f"(c.y), "+f"(c.z), "+f"(c.w)
        : "r"(a[0]), "r"(a[1]), "r"(a[2]), "r"(a[3]), "r"(b[0]), "r"(b[1]));
}
__device__ __forceinline__ uint32_t pkbf(float a, float b) {
    __nv_bfloat162 t = __floats2bfloat162_rn(a, b);
    return *reinterpret_cast<uint32_t*>(&t);
}

__device__ __forceinline__ void sample_setup(float c, int& r0, int& r1,
                                             float& w0, float& w1) {
    float pos = (c + 1.0f) * 63.5f;
    float f0  = floorf(pos);
    float fr  = pos - f0;
    int i0 = (int)f0;
    int i1 = i0 + 1;
    w0 = ((unsigned)i0 < (unsigned)LTAB) ? (1.0f - fr) : 0.0f;
    w1 = ((unsigned)i1 < (unsigned)LTAB) ? fr : 0.0f;
    r0 = min(max(i0, 0), LTAB - 1);
    r1 = min(max(i1, 0), LTAB - 1);
}

// 8 features (this lane's quarter-block channels) for one point.
__device__ __forceinline__ void feats8(const float* __restrict__ sT, int qoff,
                                       float cx, float cy, float cz,
                                       float* __restrict__ f) {
    int xr0, xr1, yr0, yr1, zr0, zr1;
    float xw0, xw1, yw0, yw1, zw0, zw1;
    sample_setup(cx, xr0, xr1, xw0, xw1);
    sample_setup(cy, yr0, yr1, yw0, yw1);
    sample_setup(cz, zr0, zr1, zw0, zw1);

    const float4* X0 = reinterpret_cast<const float4*>(&sT[(0 * LTAB + xr0) * TSTRIDE + qoff]);
    const float4* X1 = reinterpret_cast<const float4*>(&sT[(0 * LTAB + xr1) * TSTRIDE + qoff]);
    const float4* Y0 = reinterpret_cast<const float4*>(&sT[(1 * LTAB + yr0) * TSTRIDE + qoff]);
    const float4* Y1 = reinterpret_cast<const float4*>(&sT[(1 * LTAB + yr1) * TSTRIDE + qoff]);
    const float4* Z0 = reinterpret_cast<const float4*>(&sT[(2 * LTAB + zr0) * TSTRIDE + qoff]);
    const float4* Z1 = reinterpret_cast<const float4*>(&sT[(2 * LTAB + zr1) * TSTRIDE + qoff]);

    const float invR  = 2.5f;
    const float invR2 = 6.25f;

#define FEAT1(OUT, X0v, X1v, Y0v, Y1v, Z0v, Z1v)            \
    {                                                       \
        float xv = fmaf((X1v), xw1, (X0v) * xw0);           \
        float yv = fmaf((Y1v), yw1, (Y0v) * yw0);           \
        float zv = fmaf((Z1v), zw1, (Z0v) * zw0);           \
        float s  = xv + yv + zv;                            \
        float xy = xv * yv;                                 \
        float p2 = fmaf(xv, zv, xy);                        \
        p2 = fmaf(yv, zv, p2);                              \
        float p3 = xy * zv;                                 \
        float fv = fmaf(p2, invR, s);                       \
        OUT = fmaf(p3, invR2, fv);                          \
    }
#pragma unroll
    for (int hlf = 0; hlf < 2; hlf++) {
        float4 xa0 = X0[hlf], xa1 = X1[hlf];
        float4 ya0 = Y0[hlf], ya1 = Y1[hlf];
        float4 za0 = Z0[hlf], za1 = Z1[hlf];
        FEAT1(f[4 * hlf + 0], xa0.x, xa1.x, ya0.x, ya1.x, za0.x, za1.x);
        FEAT1(f[4 * hlf + 1], xa0.y, xa1.y, ya0.y, ya1.y, za0.y, za1.y);
        FEAT1(f[4 * hlf + 2], xa0.z, xa1.z, ya0.z, ya1.z, za0.z, za1.z);
        FEAT1(f[4 * hlf + 3], xa0.w, xa1.w, ya0.w, ya1.w, za0.w, za1.w);
    }
#undef FEAT1
}

__global__ __launch_bounds__(NTHREADS, 2)
void rank1_hmma_kernel(const float* __restrict__ coords,
                       const float* __restrict__ lines,
                       const float* __restrict__ W1,
                       const float* __restrict__ b1,
                       const float* __restrict__ W2,
                       const float* __restrict__ b2,
                       float* __restrict__ out, int M) {
    extern __shared__ char smc[];
    const uint32_t sb = smem_u32(smc);
    float* sT  = reinterpret_cast<float*>(smc + SM_TAB);
    float* sb1 = reinterpret_cast<float*>(smc + SM_B1);
    float* sW2 = reinterpret_cast<float*>(smc + SM_W2);

    const int tid  = threadIdx.x;
    const int wid  = tid >> 5;
    const int lane = tid & 31;

    // ---- stage table: per row, 4 quarter-blocks of 8 permuted channels ----
    // block q holds channels {2q,2q+1,2q+8,2q+9,2q+16,2q+17,2q+24,2q+25}
    for (int idx = tid; idx < 3 * LTAB; idx += NTHREADS) {
        const float* src = lines + idx * CL;
        float v[CL];
#pragma unroll
        for (int j = 0; j < 8; j++) {
            float4 t4 = reinterpret_cast<const float4*>(src)[j];
            v[4 * j + 0] = t4.x; v[4 * j + 1] = t4.y;
            v[4 * j + 2] = t4.z; v[4 * j + 3] = t4.w;
        }
        float* dst = sT + idx * TSTRIDE;
#pragma unroll
        for (int q = 0; q < 4; q++) {
            dst[8 * q + 0] = v[2 * q];      dst[8 * q + 1] = v[2 * q + 1];
            dst[8 * q + 2] = v[2 * q + 8];  dst[8 * q + 3] = v[2 * q + 9];
            dst[8 * q + 4] = v[2 * q + 16]; dst[8 * q + 5] = v[2 * q + 17];
            dst[8 * q + 6] = v[2 * q + 24]; dst[8 * q + 7] = v[2 * q + 25];
        }
    }
    // ---- stage b1, W2, split-bf16 W1 = [wh | wl] (channel order identity) ----
    if (tid < HDIM) {
        sb1[tid] = b1[tid];
        sW2[tid] = W2[tid];
        char* dst = smc + SM_W1 + tid * ROWPAD;
        const float4* wrow = reinterpret_cast<const float4*>(W1 + tid * CL);
#pragma unroll
        for (int j = 0; j < 8; j += 2) {
            float4 wa = wrow[j], wb = wrow[j + 1];
            float ha0 = __bfloat162float(__float2bfloat16(wa.x));
            float ha1 = __bfloat162float(__float2bfloat16(wa.y));
            float ha2 = __bfloat162float(__float2bfloat16(wa.z));
            float ha3 = __bfloat162float(__float2bfloat16(wa.w));
            float hb0 = __bfloat162float(__float2bfloat16(wb.x));
            float hb1 = __bfloat162float(__float2bfloat16(wb.y));
            float hb2 = __bfloat162float(__float2bfloat16(wb.z));
            float hb3 = __bfloat162float(__float2bfloat16(wb.w));
            uint4 vh = make_uint4(pkbf(ha0, ha1), pkbf(ha2, ha3),
                                  pkbf(hb0, hb1), pkbf(hb2, hb3));
            uint4 vl = make_uint4(pkbf(wa.x - ha0, wa.y - ha1),
                                  pkbf(wa.z - ha2, wa.w - ha3),
                                  pkbf(wb.x - hb0, wb.y - hb1),
                                  pkbf(wb.z - hb2, wb.w - hb3));
            *reinterpret_cast<uint4*>(dst + j * 8)      = vh;
            *reinterpret_cast<uint4*>(dst + 64 + j * 8) = vl;
        }
    }
    __syncthreads();

    const float bias2 = __ldg(b2);
    const uint32_t sbW1 = sb + SM_W1;

    // B ldmatrix addressing (identical to R4)
    const uint32_t b_row = (uint32_t)((lane & 7) + ((lane & 16) ? 8 : 0));
    const uint32_t b_addr_base =
        sbW1 + b_row * ROWPAD + (uint32_t)((lane & 8) ? 16 : 0);

    const int qoff = (lane & 3) * 8;
    const int base = lane >> 2;

    const int warp_gid    = blockIdx.x * WARPS_PER_CTA + wid;
    const int total_warps = NBLOCKS * WARPS_PER_CTA;
    const int tiles       = (M + 31) >> 5;

    for (int t = warp_gid; t < tiles; t += total_warps) {
        // ---- build A fragments in registers: 4 points per lane ----
        uint32_t afr[2][4][4];   // [row-tile][k-chunk][frag reg]
#pragma unroll
        for (int pi = 0; pi < 4; pi++) {
            int prow = base + pi * 8;
            int p  = t * 32 + prow;
            int pc = (p < M) ? p : (M - 1);
            float cx = __ldg(&coords[3 * pc + 0]);
            float cy = __ldg(&coords[3 * pc + 1]);
            float cz = __ldg(&coords[3 * pc + 2]);
            float f[8];
            feats8(sT, qoff, cx, cy, cz, f);

            float h[8], l[8];
#pragma unroll
            for (int u = 0; u < 8; u++) {
                h[u] = __bfloat162float(__float2bfloat16(f[u]));
                l[u] = f[u] - h[u];
            }
            int rt = pi >> 1;
            int rs = pi & 1;
            afr[rt][0][rs]     = pkbf(h[0], h[1]);
            afr[rt][0][2 + rs] = pkbf(h[2], h[3]);
            afr[rt][1][rs]     = pkbf(h[4], h[5]);
            afr[rt][1][2 + rs] = pkbf(h[6], h[7]);
            afr[rt][2][rs]     = pkbf(l[0], l[1]);
            afr[rt][2][2 + rs] = pkbf(l[2], l[3]);
            afr[rt][3][rs]     = pkbf(l[4], l[5]);
            afr[rt][3][2 + rs] = pkbf(l[6], l[7]);
        }

        float oacc0 = 0.0f, oacc1 = 0.0f, oacc2 = 0.0f, oacc3 = 0.0f;
        const int colb = (lane & 3) * 2;

#pragma unroll
        for (int np = 0; np < 8; np++) {
            uint32_t b[4][4];  // [k16 chunk][ntile0 b0,b1, ntile1 b0,b1]
#pragma unroll
            for (int kc = 0; kc < 4; kc++)
                ldsm_x4(b_addr_base + (uint32_t)(np * 16) * ROWPAD +
                            (uint32_t)(kc * 32),
                        b[kc]);

            float4 c[2][2];
#pragma unroll
            for (int rt = 0; rt < 2; rt++)
#pragma unroll
                for (int nt = 0; nt < 2; nt++)
                    c[rt][nt] = make_float4(0.f, 0.f, 0.f, 0.f);

#pragma unroll
            for (int rt = 0; rt < 2; rt++) {
#pragma unroll
                for (int nt = 0; nt < 2; nt++) {
                    mma_bf16(c[rt][nt], afr[rt][0], &b[0][nt * 2]);  // fh*wh k0
                    mma_bf16(c[rt][nt], afr[rt][1], &b[1][nt * 2]);  // fh*wh k1
                    mma_bf16(c[rt][nt], afr[rt][0], &b[2][nt * 2]);  // fh*wl k0
                    mma_bf16(c[rt][nt], afr[rt][1], &b[3][nt * 2]);  // fh*wl k1
                    mma_bf16(c[rt][nt], afr[rt][2], &b[0][nt * 2]);  // fl*wh k0
                    mma_bf16(c[rt][nt], afr[rt][3], &b[1][nt * 2]);  // fl*wh k1
                }
            }

            // ---- fused epilogue on fragments ----
            int col0 = np * 16 + colb;
            float2 b1a = *reinterpret_cast<const float2*>(&sb1[col0]);
            float2 w2a = *reinterpret_cast<const float2*>(&sW2[col0]);
            float2 b1b = *reinterpret_cast<const float2*>(&sb1[col0 + 8]);
            float2 w2b = *reinterpret_cast<const float2*>(&sW2[col0 + 8]);
#pragma unroll
            for (int rt = 0; rt < 2; rt++) {
                float lo = 0.0f, hi = 0.0f;
                lo = fmaf(fmaxf(c[rt][0].x + b1a.x, 0.f), w2a.x, lo);
                lo = fmaf(fmaxf(c[rt][0].y + b1a.y, 0.f), w2a.y, lo);
                lo = fmaf(fmaxf(c[rt][1].x + b1b.x, 0.f), w2b.x, lo);
                lo = fmaf(fmaxf(c[rt][1].y + b1b.y, 0.f), w2b.y, lo);
                hi = fmaf(fmaxf(c[rt][0].z + b1a.x, 0.f), w2a.x, hi);
                hi = fmaf(fmaxf(c[rt][0].w + b1a.y, 0.f), w2a.y, hi);
                hi = fmaf(fmaxf(c[rt][1].z + b1b.x, 0.f), w2b.x, hi);
                hi = fmaf(fmaxf(c[rt][1].w + b1b.y, 0.f), w2b.y, hi);
                if (rt == 0) { oacc0 += lo; oacc1 += hi; }
                else         { oacc2 += lo; oacc3 += hi; }
            }
        }

        // ---- reduce over the 4 lanes sharing each row ----
        oacc0 += __shfl_xor_sync(0xffffffffu, oacc0, 1);
        oacc0 += __shfl_xor_sync(0xffffffffu, oacc0, 2);
        oacc1 += __shfl_xor_sync(0xffffffffu, oacc1, 1);
        oacc1 += __shfl_xor_sync(0xffffffffu, oacc1, 2);
        oacc2 += __shfl_xor_sync(0xffffffffu, oacc2, 1);
        oacc2 += __shfl_xor_sync(0xffffffffu, oacc2, 2);
        oacc3 += __shfl_xor_sync(0xffffffffu, oacc3, 1);
        oacc3 += __shfl_xor_sync(0xffffffffu, oacc3, 2);

        if ((lane & 3) == 0) {
            int r  = lane >> 2;
            int pb = t * 32;
            if (pb + r      < M) out[pb + r]      = oacc0 + bias2;
            if (pb + r + 8  < M) out[pb + r + 8]  = oacc1 + bias2;
            if (pb + r + 16 < M) out[pb + r + 16] = oacc2 + bias2;
            if (pb + r + 24 < M) out[pb + r + 24] = oacc3 + bias2;
        }
    }
}

extern "C" void kernel_launch(void* const* d_in, const int* in_sizes, int n_in,
                              void* d_out, int out_size) {
    const float* coords = (const float*)d_in[0];
    const float* lines  = (const float*)d_in[1];
    const float* W1     = (const float*)d_in[2];
    const float* b1     = (const float*)d_in[3];
    const float* W2     = (const float*)d_in[4];
    const float* b2     = (const float*)d_in[5];
    float* out = (float*)d_out;

    int M = in_sizes[0] / 3;

    cudaFuncSetAttribute(rank1_hmma_kernel,
                         cudaFuncAttributeMaxDynamicSharedMemorySize, SMEM_BYTES);

    rank1_hmma_kernel<<<NBLOCKS, NTHREADS, SMEM_BYTES>>>(
        coords, lines, W1, b1, W2, b2, out, M);
}